// round 14
// baseline (speedup 1.0000x reference)
#include <cuda_runtime.h>
#include <cuda_bf16.h>
#include <math.h>

// S4D kernel init via warp-level TF32 mma.sync (baseline PTX, compute_103).
// out[h, j*128+i] = D[j,i] of D[32x128] = A[32x64] * B[64x128],
//   K channels: k=n -> (A=Px, B=Qr); k=32+n -> (A=-Py, B=Qi).
// 2-pass TF32: A (P) exact as pre-split hi+lo; B (Q) single tf32.
//
// Round-13: k-axis stored PERMUTED, p = (k&~15)|((k&3)<<2)|((k>>2)&3), so each
// mma fragment's k-values {t,t+4,t+8,t+12} are 4 consecutive words -> every
// fragment load is ONE LDS.128. Mainloop LDS instructions: 768 -> 192 per
// block (LSU-issue was the binding pipe). Wavefronts/banks unchanged-clean.

#define NTH 128
#define N2  32
#define TT  128
#define QP  68          // smem row pitch in 32-bit words

typedef unsigned int u32;

// dynamic smem layout (32-bit word offsets)
#define OFF_Q    0                      // u32 tf32 [128][QP]  (k permuted)
#define OFF_PH   (OFF_Q  + TT * QP)     // u32 tf32-hi [32][QP]
#define OFF_PL   (OFF_PH + N2 * QP)     // u32 tf32-lo [32][QP]
#define OFF_POW  (OFF_PL + N2 * QP)     // float2 [32][12]
#define OFF_CCF  (OFF_POW + N2 * 24)    // float2 [32]
#define SMEM_W   (OFF_CCF + 64)
#define SMEM_B   (SMEM_W * 4)

__device__ __forceinline__ int kperm(int k) {
    return (k & ~15) | ((k & 3) << 2) | ((k >> 2) & 3);
}
__device__ __forceinline__ float2 cmul(float2 a, float2 b) {
    return make_float2(a.x * b.x - a.y * b.y, a.x * b.y + a.y * b.x);
}
__device__ __forceinline__ u32 tf32_hi(float x) {
    u32 t; asm("cvt.rna.tf32.f32 %0, %1;" : "=r"(t) : "f"(x)); return t;
}
__device__ __forceinline__ void tf32_split(float x, u32& hi, u32& lo) {
    hi = tf32_hi(x);
    lo = tf32_hi(x - __uint_as_float(hi));
}
__device__ __forceinline__ void mma_tf32(float* c, u32 a0, u32 a1, u32 a2, u32 a3,
                                         u32 b0, u32 b1) {
    asm volatile(
        "mma.sync.aligned.m16n8k8.row.col.f32.tf32.tf32.f32 "
        "{%0,%1,%2,%3}, {%4,%5,%6,%7}, {%8,%9}, {%0,%1,%2,%3};"
        : "+f"(c[0]), "+f"(c[1]), "+f"(c[2]), "+f"(c[3])
        : "r"(a0), "r"(a1), "r"(a2), "r"(a3), "r"(b0), "r"(b1));
}

__global__ __launch_bounds__(NTH, 4)
void s4d_mma_kernel(
    const float* __restrict__ log_dt,
    const float* __restrict__ C,          // (H, 32, 2)
    const float* __restrict__ lAr,        // (H, 32)
    const float* __restrict__ Aim,        // (H, 32)
    float* __restrict__ out,              // (H, L)
    int L)
{
    extern __shared__ u32 smw[];
    u32*    sQ   = smw + OFF_Q;          // [i][p]
    u32*    sPh  = smw + OFF_PH;         // [j][p] hi
    u32*    sPl  = smw + OFF_PL;         // [j][p] lo
    float2* sPow = (float2*)(smw + OFF_POW);
    float2* sCcf = (float2*)(smw + OFF_CCF);

    const int h = blockIdx.x, tid = threadIdx.x;
    const int wid = tid >> 5, lane = tid & 31;
    const int g = lane >> 2, t = lane & 3;      // mma quad coords

    // ---------- Phase 0: per-n coefficients + power table ----------
    if (tid < N2) {
        const int n = tid, gg = h * N2 + n;
        float dt  = expf(log_dt[h]);
        float ar0 = -expf(lAr[gg]);
        float ai0 = Aim[gg];
        float e = expf(ar0 * dt), s, c;
        sincosf(ai0 * dt, &s, &c);
        float2 z = make_float2(e * c, e * s);   // w = exp(dtA)
        #pragma unroll
        for (int k = 0; k < 12; k++) {
            sPow[n * 12 + k] = z;
            z = make_float2(z.x * z.x - z.y * z.y, 2.0f * z.x * z.y);
        }
        float2 w0 = sPow[n * 12];
        float Er = w0.x - 1.0f, Ei = w0.y;
        float inv = 1.0f / (ar0 * ar0 + ai0 * ai0);
        float Dr = (Er * ar0 + Ei * ai0) * inv;
        float Di = (Ei * ar0 - Er * ai0) * inv;
        float cr = C[2 * gg], ci = C[2 * gg + 1];
        sCcf[n] = make_float2(2.0f * (cr * Dr - ci * Di),
                              2.0f * (cr * Di + ci * Dr));
    }
    __syncthreads();

    // ---------- Q: recurrence (n=lane, seg=wid), store tf32 at permuted k ----------
    {
        const int n = lane, seg = wid;           // 4 segs of 32 i
        const int pn = kperm(n);                 // k=n ; k=32+n -> pn+32
        float2 z = sCcf[n];
        if (seg & 1) z = cmul(z, sPow[n * 12 + 5]);   // w^32
        if (seg & 2) z = cmul(z, sPow[n * 12 + 6]);   // w^64
        float2 w = sPow[n * 12];
        #pragma unroll
        for (int k = 0; k < 32; k++) {
            int i = seg * 32 + k;
            sQ[i * QP + pn]      = tf32_hi(z.x); // banks: bijection, clean
            sQ[i * QP + pn + 32] = tf32_hi(z.y);
            z = cmul(z, w);
        }
    }
    // ---------- P: w^(128j), pre-split hi/lo at permuted k ----------
    #pragma unroll
    for (int r = 0; r < 8; r++) {
        int idx = r * NTH + tid;
        int n = idx & 31, j = idx >> 5;          // j = r*4 + wid
        float2 z = make_float2(1.0f, 0.0f);
        if (j & 1)  z = cmul(z, sPow[n * 12 + 7]);
        if (j & 2)  z = cmul(z, sPow[n * 12 + 8]);
        if (j & 4)  z = cmul(z, sPow[n * 12 + 9]);
        if (j & 8)  z = cmul(z, sPow[n * 12 + 10]);
        if (j & 16) z = cmul(z, sPow[n * 12 + 11]);
        u32 hx, lx, hy, ly;
        tf32_split(z.x, hx, lx);                 // Px
        tf32_split(-z.y, hy, ly);                // -Py
        const int pn = kperm(n);
        sPh[j * QP + pn]      = hx;
        sPh[j * QP + pn + 32] = hy;
        sPl[j * QP + pn]      = lx;
        sPl[j * QP + pn + 32] = ly;
    }
    __syncthreads();

    // ---------- Mainloop: warp w covers i in [32w, 32w+32); 4 k16 chunks ----------
    float acc[2][4][4];
    #pragma unroll
    for (int mt = 0; mt < 2; mt++)
        #pragma unroll
        for (int nt = 0; nt < 4; nt++)
            #pragma unroll
            for (int c = 0; c < 4; c++) acc[mt][nt][c] = 0.0f;

    #pragma unroll
    for (int c = 0; c < 4; c++) {
        const int kc = 16 * c + 4 * t;           // physical column base
        // A fragments (P) hi/lo: one LDS.128 per row-group
        uint4 Ah[2][2], Al[2][2];
        #pragma unroll
        for (int mt = 0; mt < 2; mt++) {
            int r0 = (16 * mt + g) * QP + kc;
            int r1 = r0 + 8 * QP;
            Ah[mt][0] = *(const uint4*)&sPh[r0];
            Ah[mt][1] = *(const uint4*)&sPh[r1];
            Al[mt][0] = *(const uint4*)&sPl[r0];
            Al[mt][1] = *(const uint4*)&sPl[r1];
        }
        // B fragments (Q): one LDS.128 per n-tile
        uint4 B[4];
        #pragma unroll
        for (int nt = 0; nt < 4; nt++)
            B[nt] = *(const uint4*)&sQ[(32 * wid + 8 * nt + g) * QP + kc];

        // hi pass: two k8 sub-steps per chunk
        #pragma unroll
        for (int mt = 0; mt < 2; mt++)
            #pragma unroll
            for (int nt = 0; nt < 4; nt++) {
                mma_tf32(acc[mt][nt], Ah[mt][0].x, Ah[mt][1].x, Ah[mt][0].y, Ah[mt][1].y,
                         B[nt].x, B[nt].y);
                mma_tf32(acc[mt][nt], Ah[mt][0].z, Ah[mt][1].z, Ah[mt][0].w, Ah[mt][1].w,
                         B[nt].z, B[nt].w);
            }
        // lo pass
        #pragma unroll
        for (int mt = 0; mt < 2; mt++)
            #pragma unroll
            for (int nt = 0; nt < 4; nt++) {
                mma_tf32(acc[mt][nt], Al[mt][0].x, Al[mt][1].x, Al[mt][0].y, Al[mt][1].y,
                         B[nt].x, B[nt].y);
                mma_tf32(acc[mt][nt], Al[mt][0].z, Al[mt][1].z, Al[mt][0].w, Al[mt][1].w,
                         B[nt].z, B[nt].w);
            }
    }

    // ---------- Epilogue: D[j,i] -> out[h, j*128 + i], float2 stores ----------
    float* op = out + (size_t)h * (size_t)L;
    #pragma unroll
    for (int mt = 0; mt < 2; mt++) {
        #pragma unroll
        for (int nt = 0; nt < 4; nt++) {
            int j0 = 16 * mt + g;
            int i0 = 32 * wid + 8 * nt + 2 * t;
            *(float2*)&op[j0 * TT + i0]       = make_float2(acc[mt][nt][0], acc[mt][nt][1]);
            *(float2*)&op[(j0 + 8) * TT + i0] = make_float2(acc[mt][nt][2], acc[mt][nt][3]);
        }
    }
}

extern "C" void kernel_launch(void* const* d_in, const int* in_sizes, int n_in,
                              void* d_out, int out_size) {
    // inputs: [0]=L (scalar), [1]=log_dt (H), [2]=C (H,32,2),
    //         [3]=log_A_real (H,32), [4]=A_imag (H,32)
    const float* log_dt = (const float*)d_in[1];
    const float* C      = (const float*)d_in[2];
    const float* lAr    = (const float*)d_in[3];
    const float* Aim    = (const float*)d_in[4];
    float* out = (float*)d_out;

    int H = in_sizes[1];          // 1024
    int L = out_size / H;         // 4096

    cudaFuncSetAttribute(s4d_mma_kernel,
                         cudaFuncAttributeMaxDynamicSharedMemorySize, SMEM_B);
    s4d_mma_kernel<<<H, NTH, SMEM_B>>>(log_dt, C, lAr, Aim, out, L);
}

// round 15
// speedup vs baseline: 1.2937x; 1.2937x over previous
#include <cuda_runtime.h>
#include <cuda_bf16.h>
#include <math.h>

// S4D kernel init via warp-level TF32 mma.sync (baseline PTX, compute_103).
// out[h, j*128+i] = D[j,i] of D[32x128] = A[32x64] * B[64x128],
//   K channels: k=n -> (A=Px, B=Qr); k=32+n -> (A=-Py, B=Qi).
//
// Round-14: single-pass pure TF32 (both operands tf32-rounded once in the
// prologue). Error budget: B-only truncation measured 2.06e-4; A adds the
// same independent error in quadrature -> ~2.9e-4 << 1e-3 threshold.
// Cuts tensor work 2x, mainloop LDS 768->512/block, smem 64KB->45.8KB
// (3 -> 4 CTAs/SM). Layout identical to the validated round-12 kernel.

#define NTH 128
#define N2  32
#define TT  128
#define QP  68          // smem row pitch (words); 4g+t bank-conflict-free

typedef unsigned int u32;

// dynamic smem layout (32-bit word offsets)
#define OFF_Q    0                      // u32 tf32 [128][QP]
#define OFF_PH   (OFF_Q  + TT * QP)     // u32 tf32 [32][QP]
#define OFF_POW  (OFF_PH + N2 * QP)     // float2 [32][12]
#define OFF_CCF  (OFF_POW + N2 * 24)    // float2 [32]
#define SMEM_W   (OFF_CCF + 64)
#define SMEM_B   (SMEM_W * 4)           // 46848 B

__device__ __forceinline__ float2 cmul(float2 a, float2 b) {
    return make_float2(a.x * b.x - a.y * b.y, a.x * b.y + a.y * b.x);
}
__device__ __forceinline__ u32 tf32_hi(float x) {
    u32 t; asm("cvt.rna.tf32.f32 %0, %1;" : "=r"(t) : "f"(x)); return t;
}
__device__ __forceinline__ void mma_tf32(float* c, const u32* a, const u32* b) {
    asm volatile(
        "mma.sync.aligned.m16n8k8.row.col.f32.tf32.tf32.f32 "
        "{%0,%1,%2,%3}, {%4,%5,%6,%7}, {%8,%9}, {%0,%1,%2,%3};"
        : "+f"(c[0]), "+f"(c[1]), "+f"(c[2]), "+f"(c[3])
        : "r"(a[0]), "r"(a[1]), "r"(a[2]), "r"(a[3]), "r"(b[0]), "r"(b[1]));
}

__global__ __launch_bounds__(NTH)
void s4d_mma_kernel(
    const float* __restrict__ log_dt,
    const float* __restrict__ C,          // (H, 32, 2)
    const float* __restrict__ lAr,        // (H, 32)
    const float* __restrict__ Aim,        // (H, 32)
    float* __restrict__ out,              // (H, L)
    int L)
{
    extern __shared__ u32 smw[];
    u32*    sQ   = smw + OFF_Q;          // [i][k] tf32: k=n -> Qr, k=32+n -> Qi
    u32*    sPh  = smw + OFF_PH;         // [j][k] tf32: k=n -> Px, k=32+n -> -Py
    float2* sPow = (float2*)(smw + OFF_POW);
    float2* sCcf = (float2*)(smw + OFF_CCF);

    const int h = blockIdx.x, tid = threadIdx.x;
    const int wid = tid >> 5, lane = tid & 31;
    const int g = lane >> 2, t = lane & 3;      // mma quad coords

    // ---------- Phase 0: per-n coefficients + power table ----------
    if (tid < N2) {
        const int n = tid, gg = h * N2 + n;
        float dt  = expf(log_dt[h]);
        float ar0 = -expf(lAr[gg]);
        float ai0 = Aim[gg];
        float e = expf(ar0 * dt), s, c;
        sincosf(ai0 * dt, &s, &c);
        float2 z = make_float2(e * c, e * s);   // w = exp(dtA)
        #pragma unroll
        for (int k = 0; k < 12; k++) {
            sPow[n * 12 + k] = z;
            z = make_float2(z.x * z.x - z.y * z.y, 2.0f * z.x * z.y);
        }
        float2 w0 = sPow[n * 12];
        float Er = w0.x - 1.0f, Ei = w0.y;
        float inv = 1.0f / (ar0 * ar0 + ai0 * ai0);
        float Dr = (Er * ar0 + Ei * ai0) * inv;
        float Di = (Ei * ar0 - Er * ai0) * inv;
        float cr = C[2 * gg], ci = C[2 * gg + 1];
        sCcf[n] = make_float2(2.0f * (cr * Dr - ci * Di),
                              2.0f * (cr * Di + ci * Dr));
    }
    __syncthreads();

    // ---------- Q: recurrence, thread (n=lane, seg=wid), store tf32 ----------
    {
        const int n = lane, seg = wid;           // 4 segs of 32 i
        float2 z = sCcf[n];
        if (seg & 1) z = cmul(z, sPow[n * 12 + 5]);   // w^32
        if (seg & 2) z = cmul(z, sPow[n * 12 + 6]);   // w^64
        float2 w = sPow[n * 12];
        #pragma unroll
        for (int k = 0; k < 32; k++) {
            int i = seg * 32 + k;
            sQ[i * QP + n]      = tf32_hi(z.x);  // bank 4i+n: conflict-free
            sQ[i * QP + n + 32] = tf32_hi(z.y);
            z = cmul(z, w);
        }
    }
    // ---------- P: w^(128j), single tf32 ----------
    #pragma unroll
    for (int r = 0; r < 8; r++) {
        int idx = r * NTH + tid;
        int n = idx & 31, j = idx >> 5;          // j = r*4 + wid
        float2 z = make_float2(1.0f, 0.0f);
        if (j & 1)  z = cmul(z, sPow[n * 12 + 7]);
        if (j & 2)  z = cmul(z, sPow[n * 12 + 8]);
        if (j & 4)  z = cmul(z, sPow[n * 12 + 9]);
        if (j & 8)  z = cmul(z, sPow[n * 12 + 10]);
        if (j & 16) z = cmul(z, sPow[n * 12 + 11]);
        sPh[j * QP + n]      = tf32_hi(z.x);     // Px
        sPh[j * QP + n + 32] = tf32_hi(-z.y);    // -Py
    }
    __syncthreads();

    // ---------- Mainloop: warp w covers i in [32w, 32w+32) = 4 n-tiles ----------
    float acc[2][4][4];
    #pragma unroll
    for (int mt = 0; mt < 2; mt++)
        #pragma unroll
        for (int nt = 0; nt < 4; nt++)
            #pragma unroll
            for (int c = 0; c < 4; c++) acc[mt][nt][c] = 0.0f;

    #pragma unroll
    for (int ks = 0; ks < 8; ks++) {
        const int kb = 8 * ks;
        // A fragments (P), single tf32 (no alu)
        u32 a[2][4];
        #pragma unroll
        for (int mt = 0; mt < 2; mt++) {
            int r0 = (16 * mt + g) * QP, r1 = (16 * mt + g + 8) * QP;
            a[mt][0] = sPh[r0 + kb + t];
            a[mt][1] = sPh[r1 + kb + t];
            a[mt][2] = sPh[r0 + kb + t + 4];
            a[mt][3] = sPh[r1 + kb + t + 4];
        }
        // B fragments (Q), tf32 (no alu)
        u32 b[4][2];
        #pragma unroll
        for (int nt = 0; nt < 4; nt++) {
            int ib = 32 * wid + 8 * nt;
            b[nt][0] = sQ[(ib + g) * QP + kb + t];
            b[nt][1] = sQ[(ib + g) * QP + kb + t + 4];
        }
        // single pass
        #pragma unroll
        for (int mt = 0; mt < 2; mt++)
            #pragma unroll
            for (int nt = 0; nt < 4; nt++)
                mma_tf32(acc[mt][nt], a[mt], b[nt]);
    }

    // ---------- Epilogue: D[j,i] -> out[h, j*128 + i], float2 stores ----------
    float* op = out + (size_t)h * (size_t)L;
    #pragma unroll
    for (int mt = 0; mt < 2; mt++) {
        #pragma unroll
        for (int nt = 0; nt < 4; nt++) {
            int j0 = 16 * mt + g;
            int i0 = 32 * wid + 8 * nt + 2 * t;
            *(float2*)&op[j0 * TT + i0]       = make_float2(acc[mt][nt][0], acc[mt][nt][1]);
            *(float2*)&op[(j0 + 8) * TT + i0] = make_float2(acc[mt][nt][2], acc[mt][nt][3]);
        }
    }
}

extern "C" void kernel_launch(void* const* d_in, const int* in_sizes, int n_in,
                              void* d_out, int out_size) {
    // inputs: [0]=L (scalar), [1]=log_dt (H), [2]=C (H,32,2),
    //         [3]=log_A_real (H,32), [4]=A_imag (H,32)
    const float* log_dt = (const float*)d_in[1];
    const float* C      = (const float*)d_in[2];
    const float* lAr    = (const float*)d_in[3];
    const float* Aim    = (const float*)d_in[4];
    float* out = (float*)d_out;

    int H = in_sizes[1];          // 1024
    int L = out_size / H;         // 4096

    cudaFuncSetAttribute(s4d_mma_kernel,
                         cudaFuncAttributeMaxDynamicSharedMemorySize, SMEM_B);
    s4d_mma_kernel<<<H, NTH, SMEM_B>>>(log_dt, C, lAr, Aim, out, L);
}